// round 3
// baseline (speedup 1.0000x reference)
#include <cuda_runtime.h>
#include <cuda_bf16.h>

// Sparsemax rows of 2048 fp32.
// For N(0,1) rows, tau* ~= 3.0. Static threshold THETA=2.0 < tau* w.h.p.:
//  - elements <= THETA are provably 0 in the output -> store zeros immediately
//    (no dependence on tau), fully streaming.
//  - the ~47 candidates > THETA are gathered to shared; warp 0 solves Michelot
//    on them. If resulting tau >= THETA it is exactly tau* (KKT self-certifies).
//  - candidate owners then rewrite just their scalars (same-thread ordering).
//  - else: full-block Michelot fallback from registers (prob ~0, correctness only).

#define ROWLEN  2048
#define THREADS 256
#define VPT     (ROWLEN / THREADS)   // 8
#define NWARP   (THREADS / 32)       // 8
#define CAP     256
#define THETA   2.0f
#define NEG_INF (-3.0e38f)

__global__ __launch_bounds__(THREADS, 8)
void sparsemax_kernel(const float* __restrict__ z, float* __restrict__ out) {
    const long long row = blockIdx.x;
    const float4* __restrict__ z4   = reinterpret_cast<const float4*>(z + row * ROWLEN);
    float4* __restrict__       out4 = reinterpret_cast<float4*>(out + row * ROWLEN);
    float* __restrict__        outp = out + row * ROWLEN;
    const int tid  = threadIdx.x;
    const int lane = tid & 31;
    const int wid  = tid >> 5;

    __shared__ float s_cand[CAP];
    __shared__ int   s_n;
    __shared__ float s_tau;
    __shared__ int   s_ok;
    __shared__ float s_red[NWARP];
    __shared__ float s_cnt[NWARP];

    // issue loads first (latency overlap with s_n init barrier)
    float4 a = z4[tid];
    float4 b = z4[tid + THREADS];

    if (tid == 0) s_n = 0;
    __syncthreads();

    float v[VPT] = {a.x, a.y, a.z, a.w, b.x, b.y, b.z, b.w};

    // ---- stream zeros immediately: correct for every z <= THETA (<= tau*) ----
    const float4 zero4 = make_float4(0.f, 0.f, 0.f, 0.f);
    out4[tid]           = zero4;
    out4[tid + THREADS] = zero4;

    // ---- gather candidates > THETA ----
    unsigned mask = 0u;
    #pragma unroll
    for (int i = 0; i < VPT; i++) {
        if (v[i] > THETA) {
            mask |= (1u << i);
            int idx = atomicAdd(&s_n, 1);
            if (idx < CAP) s_cand[idx] = v[i];
        }
    }
    __syncthreads();
    const int n = s_n;

    // ---- warp 0: Michelot on candidate set; self-certify tau >= THETA ----
    if (wid == 0) {
        float c[CAP / 32];
        #pragma unroll
        for (int i = 0; i < CAP / 32; i++) {
            int idx = lane + 32 * i;
            c[i] = (idx < n) ? s_cand[idx] : NEG_INF;
        }
        // tau0 from full candidate set
        float s0 = 0.0f;
        #pragma unroll
        for (int i = 0; i < CAP / 32; i++) s0 += (c[i] > NEG_INF) ? c[i] : 0.0f;
        #pragma unroll
        for (int o = 16; o > 0; o >>= 1) s0 += __shfl_xor_sync(0xffffffffu, s0, o);
        float tau = (s0 - 1.0f) / (float)(n > 0 ? n : 1);
        int prev = n;
        #pragma unroll 1
        for (int it = 0; it < 64; it++) {
            float s = 0.0f, cnt = 0.0f;
            #pragma unroll
            for (int i = 0; i < CAP / 32; i++) {
                bool act = c[i] > tau;
                s   += act ? c[i] : 0.0f;
                cnt += act ? 1.0f : 0.0f;
            }
            #pragma unroll
            for (int o = 16; o > 0; o >>= 1) {
                s   += __shfl_xor_sync(0xffffffffu, s, o);
                cnt += __shfl_xor_sync(0xffffffffu, cnt, o);
            }
            if (cnt == 0.0f) break;
            tau = (s - 1.0f) / cnt;
            int k = (int)cnt;
            if (k == prev) break;
            prev = k;
        }
        if (lane == 0) {
            s_tau = tau;
            s_ok  = (n > 0 && n <= CAP && tau >= THETA) ? 1 : 0;
        }
    }
    __syncthreads();

    if (s_ok) {
        // ---- fast path: rewrite only this thread's candidates ----
        const float tau = s_tau;
        if (mask) {
            #pragma unroll
            for (int i = 0; i < VPT; i++) {
                if (mask & (1u << i)) {
                    int e = (i < 4) ? (4 * tid + i) : (4 * (tid + THREADS) + (i - 4));
                    outp[e] = fmaxf(v[i] - tau, 0.0f);
                }
            }
        }
        return;
    }

    // ---- fallback: full-block Michelot over register-resident row ----
    float tau;
    {
        float s = 0.0f;
        #pragma unroll
        for (int i = 0; i < VPT; i++) s += v[i];
        #pragma unroll
        for (int o = 16; o > 0; o >>= 1) s += __shfl_xor_sync(0xffffffffu, s, o);
        if (lane == 0) s_red[wid] = s;
        __syncthreads();
        if (tid == 0) {
            float tot = 0.0f;
            #pragma unroll
            for (int w = 0; w < NWARP; w++) tot += s_red[w];
            s_tau = (tot - 1.0f) * (1.0f / (float)ROWLEN);
        }
        __syncthreads();
        tau = s_tau;
    }
    int k_prev = ROWLEN;
    #pragma unroll 1
    for (int it = 0; it < 64; it++) {
        float s = 0.0f, cf = 0.0f;
        #pragma unroll
        for (int i = 0; i < VPT; i++) {
            bool act = v[i] > tau;
            s  += act ? v[i] : 0.0f;
            cf += act ? 1.0f : 0.0f;
        }
        #pragma unroll
        for (int o = 16; o > 0; o >>= 1) {
            s  += __shfl_xor_sync(0xffffffffu, s, o);
            cf += __shfl_xor_sync(0xffffffffu, cf, o);
        }
        if (lane == 0) { s_red[wid] = s; s_cnt[wid] = cf; }
        __syncthreads();
        if (tid == 0) {
            float ts = 0.0f, tc = 0.0f;
            #pragma unroll
            for (int w = 0; w < NWARP; w++) { ts += s_red[w]; tc += s_cnt[w]; }
            s_tau = (ts - 1.0f) / tc;
            s_cnt[0] = tc;
        }
        __syncthreads();
        tau = s_tau;
        int k = (int)s_cnt[0];
        __syncthreads();
        if (k == k_prev) break;
        k_prev = k;
    }
    float4 o0, o1;
    o0.x = fmaxf(v[0] - tau, 0.0f);
    o0.y = fmaxf(v[1] - tau, 0.0f);
    o0.z = fmaxf(v[2] - tau, 0.0f);
    o0.w = fmaxf(v[3] - tau, 0.0f);
    o1.x = fmaxf(v[4] - tau, 0.0f);
    o1.y = fmaxf(v[5] - tau, 0.0f);
    o1.z = fmaxf(v[6] - tau, 0.0f);
    o1.w = fmaxf(v[7] - tau, 0.0f);
    out4[tid]           = o0;
    out4[tid + THREADS] = o1;
}

extern "C" void kernel_launch(void* const* d_in, const int* in_sizes, int n_in,
                              void* d_out, int out_size) {
    const float* z = (const float*)d_in[0];
    float* out = (float*)d_out;
    int rows = in_sizes[0] / ROWLEN;
    sparsemax_kernel<<<rows, THREADS>>>(z, out);
}

// round 4
// speedup vs baseline: 1.1168x; 1.1168x over previous
#include <cuda_runtime.h>
#include <cuda_bf16.h>

// Sparsemax rows of 2048 fp32.
// Static threshold THETA: gather only z > THETA (~25/row for N(0,1)),
// warp 0 solves Michelot on that set; tau >= THETA self-certifies exactness
// (all discarded elements <= THETA <= tau, so KKT holds).
// Single coalesced float4 projection store. Full-block Michelot fallback for
// the (probability ~0) uncertified case keeps general correctness.

#define ROWLEN  2048
#define THREADS 256
#define VPT     (ROWLEN / THREADS)   // 8
#define NWARP   (THREADS / 32)       // 8
#define CAP     64                   // candidate capacity (mean ~25, sd ~5)
#define THETA   2.25f
#define NEG_INF (-3.0e38f)
#define FULLM   0xffffffffu

__global__ __launch_bounds__(THREADS, 8)
void sparsemax_kernel(const float* __restrict__ z, float* __restrict__ out) {
    const long long row = blockIdx.x;
    const float4* __restrict__ z4   = reinterpret_cast<const float4*>(z + row * ROWLEN);
    float4* __restrict__       out4 = reinterpret_cast<float4*>(out + row * ROWLEN);
    const int tid  = threadIdx.x;
    const int lane = tid & 31;
    const int wid  = tid >> 5;

    __shared__ float s_cand[CAP];
    __shared__ int   s_n;
    __shared__ float s_tau;
    __shared__ int   s_ok;
    __shared__ float s_red[NWARP];
    __shared__ float s_cnt[NWARP];

    // issue loads first; init + barrier overlap their latency
    float4 a = z4[tid];
    float4 b = z4[tid + THREADS];
    if (tid == 0) s_n = 0;
    __syncthreads();

    float v[VPT] = {a.x, a.y, a.z, a.w, b.x, b.y, b.z, b.w};

    // ---- ballot-compacted gather of candidates > THETA ----
    const unsigned lt = (1u << lane) - 1u;
    #pragma unroll
    for (int i = 0; i < VPT; i++) {
        bool cand = v[i] > THETA;
        unsigned ball = __ballot_sync(FULLM, cand);
        if (ball) {
            int base = 0;
            if (lane == 0) base = atomicAdd(&s_n, __popc(ball));
            base = __shfl_sync(FULLM, base, 0);
            if (cand) {
                int idx = base + __popc(ball & lt);
                if (idx < CAP) s_cand[idx] = v[i];
            }
        }
    }
    __syncthreads();
    const int n = s_n;

    // ---- warp 0: Michelot on candidate set; certify tau >= THETA ----
    if (wid == 0) {
        float c0 = (lane < n)      ? s_cand[lane]      : NEG_INF;
        float c1 = (lane + 32 < n) ? s_cand[lane + 32] : NEG_INF;
        float s0 = (c0 > NEG_INF ? c0 : 0.0f) + (c1 > NEG_INF ? c1 : 0.0f);
        #pragma unroll
        for (int o = 16; o > 0; o >>= 1) s0 += __shfl_xor_sync(FULLM, s0, o);
        float tau = (s0 - 1.0f) / (float)(n > 0 ? (n <= CAP ? n : CAP) : 1);
        int prev = -1;
        #pragma unroll 1
        for (int it = 0; it < 32; it++) {
            float s = 0.0f, cnt = 0.0f;
            bool a0 = c0 > tau, a1 = c1 > tau;
            s   += a0 ? c0 : 0.0f;    cnt += a0 ? 1.0f : 0.0f;
            s   += a1 ? c1 : 0.0f;    cnt += a1 ? 1.0f : 0.0f;
            #pragma unroll
            for (int o = 16; o > 0; o >>= 1) {
                s   += __shfl_xor_sync(FULLM, s, o);
                cnt += __shfl_xor_sync(FULLM, cnt, o);
            }
            if (cnt == 0.0f) break;
            tau = (s - 1.0f) / cnt;
            int k = (int)cnt;
            if (k == prev) break;
            prev = k;
        }
        if (lane == 0) {
            s_tau = tau;
            s_ok  = (n > 0 && n <= CAP && tau >= THETA) ? 1 : 0;
        }
    }
    __syncthreads();

    if (s_ok) {
        // ---- fast path: single coalesced projection store ----
        const float tau = s_tau;
        float4 o0, o1;
        o0.x = fmaxf(v[0] - tau, 0.0f);
        o0.y = fmaxf(v[1] - tau, 0.0f);
        o0.z = fmaxf(v[2] - tau, 0.0f);
        o0.w = fmaxf(v[3] - tau, 0.0f);
        o1.x = fmaxf(v[4] - tau, 0.0f);
        o1.y = fmaxf(v[5] - tau, 0.0f);
        o1.z = fmaxf(v[6] - tau, 0.0f);
        o1.w = fmaxf(v[7] - tau, 0.0f);
        out4[tid]           = o0;
        out4[tid + THREADS] = o1;
        return;
    }

    // ---- fallback: full-block Michelot over register-resident row ----
    float tau;
    {
        float s = 0.0f;
        #pragma unroll
        for (int i = 0; i < VPT; i++) s += v[i];
        #pragma unroll
        for (int o = 16; o > 0; o >>= 1) s += __shfl_xor_sync(FULLM, s, o);
        if (lane == 0) s_red[wid] = s;
        __syncthreads();
        if (tid == 0) {
            float tot = 0.0f;
            #pragma unroll
            for (int w = 0; w < NWARP; w++) tot += s_red[w];
            s_tau = (tot - 1.0f) * (1.0f / (float)ROWLEN);
        }
        __syncthreads();
        tau = s_tau;
    }
    int k_prev = ROWLEN;
    #pragma unroll 1
    for (int it = 0; it < 64; it++) {
        float s = 0.0f, cf = 0.0f;
        #pragma unroll
        for (int i = 0; i < VPT; i++) {
            bool act = v[i] > tau;
            s  += act ? v[i] : 0.0f;
            cf += act ? 1.0f : 0.0f;
        }
        #pragma unroll
        for (int o = 16; o > 0; o >>= 1) {
            s  += __shfl_xor_sync(FULLM, s, o);
            cf += __shfl_xor_sync(FULLM, cf, o);
        }
        if (lane == 0) { s_red[wid] = s; s_cnt[wid] = cf; }
        __syncthreads();
        if (tid == 0) {
            float ts = 0.0f, tc = 0.0f;
            #pragma unroll
            for (int w = 0; w < NWARP; w++) { ts += s_red[w]; tc += s_cnt[w]; }
            s_tau = (ts - 1.0f) / tc;
            s_cnt[0] = tc;
        }
        __syncthreads();
        tau = s_tau;
        int k = (int)s_cnt[0];
        __syncthreads();
        if (k == k_prev) break;
        k_prev = k;
    }
    float4 o0, o1;
    o0.x = fmaxf(v[0] - tau, 0.0f);
    o0.y = fmaxf(v[1] - tau, 0.0f);
    o0.z = fmaxf(v[2] - tau, 0.0f);
    o0.w = fmaxf(v[3] - tau, 0.0f);
    o1.x = fmaxf(v[4] - tau, 0.0f);
    o1.y = fmaxf(v[5] - tau, 0.0f);
    o1.z = fmaxf(v[6] - tau, 0.0f);
    o1.w = fmaxf(v[7] - tau, 0.0f);
    out4[tid]           = o0;
    out4[tid + THREADS] = o1;
}

extern "C" void kernel_launch(void* const* d_in, const int* in_sizes, int n_in,
                              void* d_out, int out_size) {
    const float* z = (const float*)d_in[0];
    float* out = (float*)d_out;
    int rows = in_sizes[0] / ROWLEN;
    sparsemax_kernel<<<rows, THREADS>>>(z, out);
}

// round 5
// speedup vs baseline: 1.1566x; 1.0357x over previous
#include <cuda_runtime.h>
#include <cuda_bf16.h>

// Sparsemax rows of 2048 fp32.
// Static threshold THETA: only z > THETA (~25/row for N(0,1)) can be in the
// support if the solved tau >= THETA (self-certifying via KKT). Warp 0 solves
// Michelot on the tiny candidate set; all threads then do one coalesced
// projection store. Touch-once data -> streaming (evict-first) cache hints.
// Full-block Michelot fallback keeps general correctness.

#define ROWLEN  2048
#define THREADS 256
#define VPT     (ROWLEN / THREADS)   // 8
#define NWARP   (THREADS / 32)       // 8
#define CAP     64
#define THETA   2.25f
#define NEG_INF (-3.0e38f)
#define FULLM   0xffffffffu

__global__ __launch_bounds__(THREADS, 8)
void sparsemax_kernel(const float* __restrict__ z, float* __restrict__ out) {
    const long long row = blockIdx.x;
    const float4* __restrict__ z4   = reinterpret_cast<const float4*>(z + row * ROWLEN);
    float4* __restrict__       out4 = reinterpret_cast<float4*>(out + row * ROWLEN);
    const int tid  = threadIdx.x;
    const int lane = tid & 31;
    const int wid  = tid >> 5;

    __shared__ float s_cand[CAP];
    __shared__ int   s_n;
    __shared__ float s_tau;
    __shared__ int   s_ok;
    __shared__ float s_red[NWARP];
    __shared__ float s_cnt[NWARP];

    // issue streaming loads first; s_n init + barrier overlap their latency
    float4 a = __ldcs(&z4[tid]);
    float4 b = __ldcs(&z4[tid + THREADS]);
    if (tid == 0) s_n = 0;
    __syncthreads();

    float v[VPT] = {a.x, a.y, a.z, a.w, b.x, b.y, b.z, b.w};

    // ---- gather candidates > THETA (max-tree prefilter, rare atomic scatter) ----
    float m = fmaxf(fmaxf(fmaxf(v[0], v[1]), fmaxf(v[2], v[3])),
                    fmaxf(fmaxf(v[4], v[5]), fmaxf(v[6], v[7])));
    if (m > THETA) {
        #pragma unroll
        for (int i = 0; i < VPT; i++) {
            if (v[i] > THETA) {
                int idx = atomicAdd(&s_n, 1);
                if (idx < CAP) s_cand[idx] = v[i];
            }
        }
    }
    __syncthreads();
    const int n = s_n;

    // ---- warp 0: Michelot on candidate set; certify tau >= THETA ----
    if (wid == 0) {
        float c0 = (lane < n)      ? s_cand[lane]      : NEG_INF;
        float c1 = (lane + 32 < n) ? s_cand[lane + 32] : NEG_INF;
        float s0 = (c0 > NEG_INF ? c0 : 0.0f) + (c1 > NEG_INF ? c1 : 0.0f);
        #pragma unroll
        for (int o = 16; o > 0; o >>= 1) s0 += __shfl_xor_sync(FULLM, s0, o);
        float tau = (s0 - 1.0f) / (float)(n > 0 ? (n <= CAP ? n : CAP) : 1);
        int prev = -1;
        #pragma unroll 1
        for (int it = 0; it < 32; it++) {
            float s = 0.0f, cnt = 0.0f;
            bool a0 = c0 > tau, a1 = c1 > tau;
            s   += a0 ? c0 : 0.0f;    cnt += a0 ? 1.0f : 0.0f;
            s   += a1 ? c1 : 0.0f;    cnt += a1 ? 1.0f : 0.0f;
            #pragma unroll
            for (int o = 16; o > 0; o >>= 1) {
                s   += __shfl_xor_sync(FULLM, s, o);
                cnt += __shfl_xor_sync(FULLM, cnt, o);
            }
            if (cnt == 0.0f) break;
            tau = (s - 1.0f) / cnt;
            int k = (int)cnt;
            if (k == prev) break;
            prev = k;
        }
        if (lane == 0) {
            s_tau = tau;
            s_ok  = (n > 0 && n <= CAP && tau >= THETA) ? 1 : 0;
        }
    }
    __syncthreads();

    if (s_ok) {
        // ---- fast path: single coalesced streaming projection store ----
        const float tau = s_tau;
        float4 o0, o1;
        o0.x = fmaxf(v[0] - tau, 0.0f);
        o0.y = fmaxf(v[1] - tau, 0.0f);
        o0.z = fmaxf(v[2] - tau, 0.0f);
        o0.w = fmaxf(v[3] - tau, 0.0f);
        o1.x = fmaxf(v[4] - tau, 0.0f);
        o1.y = fmaxf(v[5] - tau, 0.0f);
        o1.z = fmaxf(v[6] - tau, 0.0f);
        o1.w = fmaxf(v[7] - tau, 0.0f);
        __stcs(&out4[tid],           o0);
        __stcs(&out4[tid + THREADS], o1);
        return;
    }

    // ---- fallback: full-block Michelot over register-resident row ----
    float tau;
    {
        float s = 0.0f;
        #pragma unroll
        for (int i = 0; i < VPT; i++) s += v[i];
        #pragma unroll
        for (int o = 16; o > 0; o >>= 1) s += __shfl_xor_sync(FULLM, s, o);
        if (lane == 0) s_red[wid] = s;
        __syncthreads();
        if (tid == 0) {
            float tot = 0.0f;
            #pragma unroll
            for (int w = 0; w < NWARP; w++) tot += s_red[w];
            s_tau = (tot - 1.0f) * (1.0f / (float)ROWLEN);
        }
        __syncthreads();
        tau = s_tau;
    }
    int k_prev = ROWLEN;
    #pragma unroll 1
    for (int it = 0; it < 64; it++) {
        float s = 0.0f, cf = 0.0f;
        #pragma unroll
        for (int i = 0; i < VPT; i++) {
            bool act = v[i] > tau;
            s  += act ? v[i] : 0.0f;
            cf += act ? 1.0f : 0.0f;
        }
        #pragma unroll
        for (int o = 16; o > 0; o >>= 1) {
            s  += __shfl_xor_sync(FULLM, s, o);
            cf += __shfl_xor_sync(FULLM, cf, o);
        }
        if (lane == 0) { s_red[wid] = s; s_cnt[wid] = cf; }
        __syncthreads();
        if (tid == 0) {
            float ts = 0.0f, tc = 0.0f;
            #pragma unroll
            for (int w = 0; w < NWARP; w++) { ts += s_red[w]; tc += s_cnt[w]; }
            s_tau = (ts - 1.0f) / tc;
            s_cnt[0] = tc;
        }
        __syncthreads();
        tau = s_tau;
        int k = (int)s_cnt[0];
        __syncthreads();
        if (k == k_prev) break;
        k_prev = k;
    }
    float4 o0, o1;
    o0.x = fmaxf(v[0] - tau, 0.0f);
    o0.y = fmaxf(v[1] - tau, 0.0f);
    o0.z = fmaxf(v[2] - tau, 0.0f);
    o0.w = fmaxf(v[3] - tau, 0.0f);
    o1.x = fmaxf(v[4] - tau, 0.0f);
    o1.y = fmaxf(v[5] - tau, 0.0f);
    o1.z = fmaxf(v[6] - tau, 0.0f);
    o1.w = fmaxf(v[7] - tau, 0.0f);
    out4[tid]           = o0;
    out4[tid + THREADS] = o1;
}

extern "C" void kernel_launch(void* const* d_in, const int* in_sizes, int n_in,
                              void* d_out, int out_size) {
    const float* z = (const float*)d_in[0];
    float* out = (float*)d_out;
    int rows = in_sizes[0] / ROWLEN;
    sparsemax_kernel<<<rows, THREADS>>>(z, out);
}

// round 6
// speedup vs baseline: 1.2049x; 1.0417x over previous
#include <cuda_runtime.h>
#include <cuda_bf16.h>

// Sparsemax rows of 2048 fp32 — persistent grid-stride kernel.
// Each CTA processes ~74 rows; the loads for row r+stride are issued before
// the solve/store of row r, keeping the DRAM read stream continuously full
// and eliminating wave-transition bubbles.
// Static threshold THETA: candidates z > THETA (~25/row) gathered to shared;
// warp 0 solves Michelot; tau >= THETA self-certifies exactness (KKT).
// Full-block Michelot fallback (register-resident row) for the uncertified case.

#define ROWLEN  2048
#define THREADS 256
#define VPT     (ROWLEN / THREADS)   // 8
#define NWARP   (THREADS / 32)       // 8
#define F4PROW  (ROWLEN / 4)         // 512 float4 per row
#define CAP     64
#define THETA   2.25f
#define NEG_INF (-3.0e38f)
#define FULLM   0xffffffffu
#define GRID_CTAS (148 * 6)

__global__ __launch_bounds__(THREADS, 6)
void sparsemax_kernel(const float* __restrict__ z, float* __restrict__ out, int rows) {
    const float4* __restrict__ z4   = reinterpret_cast<const float4*>(z);
    float4* __restrict__       out4 = reinterpret_cast<float4*>(out);
    const int tid  = threadIdx.x;
    const int lane = tid & 31;
    const int wid  = tid >> 5;
    const long long stride = gridDim.x;

    __shared__ float s_cand[CAP];
    __shared__ int   s_n;
    __shared__ float s_tau;
    __shared__ int   s_ok;
    __shared__ float s_red[NWARP];
    __shared__ float s_cnt[NWARP];

    long long r = blockIdx.x;
    if (r >= rows) return;

    if (tid == 0) s_n = 0;

    // prime the pipeline: loads for the first row
    float4 a = __ldcs(&z4[r * F4PROW + tid]);
    float4 b = __ldcs(&z4[r * F4PROW + THREADS + tid]);
    __syncthreads();   // s_n init visible

    #pragma unroll 1
    while (true) {
        const long long rn = r + stride;
        float v[VPT] = {a.x, a.y, a.z, a.w, b.x, b.y, b.z, b.w};

        // ---- gather candidates > THETA (max-tree prefilter, rare atomics) ----
        float m = fmaxf(fmaxf(fmaxf(v[0], v[1]), fmaxf(v[2], v[3])),
                        fmaxf(fmaxf(v[4], v[5]), fmaxf(v[6], v[7])));
        if (m > THETA) {
            #pragma unroll
            for (int i = 0; i < VPT; i++) {
                if (v[i] > THETA) {
                    int idx = atomicAdd(&s_n, 1);
                    if (idx < CAP) s_cand[idx] = v[i];
                }
            }
        }

        // ---- prefetch next row BEFORE barriers/solve (hides DRAM latency) ----
        if (rn < rows) {
            a = __ldcs(&z4[rn * F4PROW + tid]);
            b = __ldcs(&z4[rn * F4PROW + THREADS + tid]);
        }
        __syncthreads();   // gather complete

        // ---- warp 0: Michelot on candidate set; certify tau >= THETA ----
        if (wid == 0) {
            const int n = s_n;
            float c0 = (lane < n)      ? s_cand[lane]      : NEG_INF;
            float c1 = (lane + 32 < n) ? s_cand[lane + 32] : NEG_INF;
            float s0 = (c0 > NEG_INF ? c0 : 0.0f) + (c1 > NEG_INF ? c1 : 0.0f);
            #pragma unroll
            for (int o = 16; o > 0; o >>= 1) s0 += __shfl_xor_sync(FULLM, s0, o);
            float tau = (s0 - 1.0f) / (float)(n > 0 ? (n <= CAP ? n : CAP) : 1);
            int prev = -1;
            #pragma unroll 1
            for (int it = 0; it < 32; it++) {
                float s = 0.0f, cnt = 0.0f;
                bool a0 = c0 > tau, a1 = c1 > tau;
                s   += a0 ? c0 : 0.0f;    cnt += a0 ? 1.0f : 0.0f;
                s   += a1 ? c1 : 0.0f;    cnt += a1 ? 1.0f : 0.0f;
                #pragma unroll
                for (int o = 16; o > 0; o >>= 1) {
                    s   += __shfl_xor_sync(FULLM, s, o);
                    cnt += __shfl_xor_sync(FULLM, cnt, o);
                }
                if (cnt == 0.0f) break;
                tau = (s - 1.0f) / cnt;
                int k = (int)cnt;
                if (k == prev) break;
                prev = k;
            }
            if (lane == 0) {
                s_tau = tau;
                s_ok  = (n > 0 && n <= CAP && tau >= THETA) ? 1 : 0;
                s_n   = 0;   // reset for next row (next gather is after barrier below)
            }
        }
        __syncthreads();   // s_tau/s_ok visible, s_n reset

        if (s_ok) {
            // ---- fast path: coalesced streaming projection store ----
            const float tau = s_tau;
            float4 o0, o1;
            o0.x = fmaxf(v[0] - tau, 0.0f);
            o0.y = fmaxf(v[1] - tau, 0.0f);
            o0.z = fmaxf(v[2] - tau, 0.0f);
            o0.w = fmaxf(v[3] - tau, 0.0f);
            o1.x = fmaxf(v[4] - tau, 0.0f);
            o1.y = fmaxf(v[5] - tau, 0.0f);
            o1.z = fmaxf(v[6] - tau, 0.0f);
            o1.w = fmaxf(v[7] - tau, 0.0f);
            __stcs(&out4[r * F4PROW + tid],           o0);
            __stcs(&out4[r * F4PROW + THREADS + tid], o1);
        } else {
            // ---- fallback: full-block Michelot over register-resident row ----
            float tau;
            {
                float s = 0.0f;
                #pragma unroll
                for (int i = 0; i < VPT; i++) s += v[i];
                #pragma unroll
                for (int o = 16; o > 0; o >>= 1) s += __shfl_xor_sync(FULLM, s, o);
                if (lane == 0) s_red[wid] = s;
                __syncthreads();
                if (tid == 0) {
                    float tot = 0.0f;
                    #pragma unroll
                    for (int w = 0; w < NWARP; w++) tot += s_red[w];
                    s_tau = (tot - 1.0f) * (1.0f / (float)ROWLEN);
                }
                __syncthreads();
                tau = s_tau;
            }
            int k_prev = ROWLEN;
            #pragma unroll 1
            for (int it = 0; it < 64; it++) {
                float s = 0.0f, cf = 0.0f;
                #pragma unroll
                for (int i = 0; i < VPT; i++) {
                    bool act = v[i] > tau;
                    s  += act ? v[i] : 0.0f;
                    cf += act ? 1.0f : 0.0f;
                }
                #pragma unroll
                for (int o = 16; o > 0; o >>= 1) {
                    s  += __shfl_xor_sync(FULLM, s, o);
                    cf += __shfl_xor_sync(FULLM, cf, o);
                }
                if (lane == 0) { s_red[wid] = s; s_cnt[wid] = cf; }
                __syncthreads();
                if (tid == 0) {
                    float ts = 0.0f, tc = 0.0f;
                    #pragma unroll
                    for (int w = 0; w < NWARP; w++) { ts += s_red[w]; tc += s_cnt[w]; }
                    s_tau = (ts - 1.0f) / tc;
                    s_cnt[0] = tc;
                }
                __syncthreads();
                tau = s_tau;
                int k = (int)s_cnt[0];
                __syncthreads();
                if (k == k_prev) break;
                k_prev = k;
            }
            float4 o0, o1;
            o0.x = fmaxf(v[0] - tau, 0.0f);
            o0.y = fmaxf(v[1] - tau, 0.0f);
            o0.z = fmaxf(v[2] - tau, 0.0f);
            o0.w = fmaxf(v[3] - tau, 0.0f);
            o1.x = fmaxf(v[4] - tau, 0.0f);
            o1.y = fmaxf(v[5] - tau, 0.0f);
            o1.z = fmaxf(v[6] - tau, 0.0f);
            o1.w = fmaxf(v[7] - tau, 0.0f);
            out4[r * F4PROW + tid]           = o0;
            out4[r * F4PROW + THREADS + tid] = o1;
        }

        if (rn >= rows) break;
        r = rn;
    }
}

extern "C" void kernel_launch(void* const* d_in, const int* in_sizes, int n_in,
                              void* d_out, int out_size) {
    const float* z = (const float*)d_in[0];
    float* out = (float*)d_out;
    int rows = in_sizes[0] / ROWLEN;
    int grid = GRID_CTAS < rows ? GRID_CTAS : rows;
    sparsemax_kernel<<<grid, THREADS>>>(z, out, rows);
}